// round 10
// baseline (speedup 1.0000x reference)
#include <cuda_runtime.h>
#include <cuda_fp16.h>
#include <cstdint>

// Problem constants
#define Bb    2
#define Tt    48
#define FQn   100
#define Dd    512
#define Hh    8
#define HDd   64
#define DFFd  2048
#define Ll    6
#define WSZw  8
#define NWw   6          // windows per batch item (T/WSZ)
#define NWIN  12         // B * NWw
#define Ss    800        // WSZ * FQ
#define HALFh 4          // ceil(WSZ/2)
#define NTOK  9600       // B*T*FQ
#define WHn   96         // NWIN * H
#define QKVLD 1536       // 3*D row stride in qkv buffer

#define QPST 68          // SMEM stride for 64-wide q/k/p tiles (≡4 mod 32)
#define VST 72           // SMEM stride for k-major V tile (≡8 mod 32)

// Flash SMEM layout (words)
#define FA_QS   0
#define FA_PS   (128 * QPST)
#define FA_KV   (FA_PS + 128 * QPST)
#define FA_REDM (FA_KV + 64 * VST)
#define FA_REDL (FA_REDM + 256)
#define FA_WORDS (FA_REDL + 256)
#define FA_BYTES (FA_WORDS * 4)

// Scratch (device globals: allocation-guard safe)
__device__ float g_x[NTOK * Dd];
__device__ float g_xw[NTOK * Dd];
__device__ float g_tmp[NTOK * Dd];
__device__ float g_attn[NTOK * Dd];
__device__ float g_qkv[NTOK * 3 * Dd];
__device__ float g_ffn[NTOK * DFFd];

// ---------------------------------------------------------------------------
// precision helpers
// ---------------------------------------------------------------------------
__device__ __forceinline__ unsigned f2tf(float f) {
    unsigned u;
    asm("cvt.rna.tf32.f32 %0, %1;" : "=r"(u) : "f"(f));
    return u;
}

__device__ __forceinline__ unsigned h2pack(float lo, float hi) {
    __half2 h = __float22half2_rn(make_float2(lo, hi));
    return *reinterpret_cast<unsigned*>(&h);
}

__device__ __forceinline__ void mma_tf32(
    float c[4], unsigned a0, unsigned a1, unsigned a2, unsigned a3,
    unsigned b0, unsigned b1)
{
    asm volatile(
        "mma.sync.aligned.m16n8k8.row.col.f32.tf32.tf32.f32 "
        "{%0,%1,%2,%3}, {%4,%5,%6,%7}, {%8,%9}, {%0,%1,%2,%3};"
        : "+f"(c[0]), "+f"(c[1]), "+f"(c[2]), "+f"(c[3])
        : "r"(a0), "r"(a1), "r"(a2), "r"(a3), "r"(b0), "r"(b1));
}

__device__ __forceinline__ void mma_fp16(
    float c[4], unsigned a0, unsigned a1, unsigned a2, unsigned a3,
    unsigned b0, unsigned b1)
{
    asm volatile(
        "mma.sync.aligned.m16n8k16.row.col.f32.f16.f16.f32 "
        "{%0,%1,%2,%3}, {%4,%5,%6,%7}, {%8,%9}, {%0,%1,%2,%3};"
        : "+f"(c[0]), "+f"(c[1]), "+f"(c[2]), "+f"(c[3])
        : "r"(a0), "r"(a1), "r"(a2), "r"(a3), "r"(b0), "r"(b1));
}

__device__ __forceinline__ uint4 tf4(float4 v) {
    return make_uint4(f2tf(v.x), f2tf(v.y), f2tf(v.z), f2tf(v.w));
}

// ---------------------------------------------------------------------------
// fp16 tensor-core NT GEMM: C[N,M] = A[N,K] @ W[M,K]^T + bias[M] (row-major)
// Block: 256 thr = 8 warps (2m x 4n), tile 128x128, K-tile 16, double-buffered.
// SMEM rows: 8 half2 words, paired order (word 2j = k-pair j, 2j+1 = pair j+4),
// XOR swizzle w ^= 2*((row>>2)&3). Fragment = one LDS.64, conflict-free.
// grid = (M/128, rows/128); rows%128==0, M%128==0, K%16==0.
// ---------------------------------------------------------------------------
__global__ __launch_bounds__(256) void gemm_tc(
    const float* __restrict__ A, int lda,
    const float* __restrict__ W, int ldw,
    const float* __restrict__ bias,
    float* __restrict__ C, int ldc,
    int K, int relu)
{
    __shared__ unsigned As[2][128 * 8];
    __shared__ unsigned Bs[2][128 * 8];
    const int tid = threadIdx.x, lane = tid & 31, wid = tid >> 5;
    const int wm = (wid & 1) << 6, wn = (wid >> 1) << 5;
    const int bm = blockIdx.y << 7, bn = blockIdx.x << 7;
    const int r8 = lane >> 2, l3 = lane & 3;
    const int lr = tid & 127;
    const int isB = tid >> 7;
    const int sw = ((lr >> 2) & 3) << 1;
    float acc[4][4][4] = {};
    const float* srcp = isB ? (W + (size_t)(bn + lr) * ldw)
                            : (A + (size_t)(bm + lr) * lda);
    float4 f0 = *(const float4*)(srcp + 0);
    float4 f1 = *(const float4*)(srcp + 4);
    float4 f2 = *(const float4*)(srcp + 8);
    float4 f3 = *(const float4*)(srcp + 12);
    {
        unsigned* dstp = (isB ? Bs[0] : As[0]) + lr * 8;
        *(uint2*)&dstp[0 ^ sw] = make_uint2(h2pack(f0.x, f0.y), h2pack(f2.x, f2.y));
        *(uint2*)&dstp[2 ^ sw] = make_uint2(h2pack(f0.z, f0.w), h2pack(f2.z, f2.w));
        *(uint2*)&dstp[4 ^ sw] = make_uint2(h2pack(f1.x, f1.y), h2pack(f3.x, f3.y));
        *(uint2*)&dstp[6 ^ sw] = make_uint2(h2pack(f1.z, f1.w), h2pack(f3.z, f3.w));
    }
    __syncthreads();
    const int T = K >> 4;
    for (int t = 0; t < T; t++) {
        const unsigned* Abuf = As[t & 1];
        const unsigned* Bbuf = Bs[t & 1];
        if (t + 1 < T) {
            srcp += 16;
            f0 = *(const float4*)(srcp + 0);
            f1 = *(const float4*)(srcp + 4);
            f2 = *(const float4*)(srcp + 8);
            f3 = *(const float4*)(srcp + 12);
        }
        uint2 alo[4], ahi[4], bfr[4];
        #pragma unroll
        for (int mt = 0; mt < 4; mt++) {
            const int r0 = wm + mt * 16 + r8;
            const int r1 = r0 + 8;
            alo[mt] = *(const uint2*)&Abuf[r0 * 8 + ((l3 << 1) ^ (((r0 >> 2) & 3) << 1))];
            ahi[mt] = *(const uint2*)&Abuf[r1 * 8 + ((l3 << 1) ^ (((r1 >> 2) & 3) << 1))];
        }
        #pragma unroll
        for (int nt = 0; nt < 4; nt++) {
            const int nr = wn + nt * 8 + r8;
            bfr[nt] = *(const uint2*)&Bbuf[nr * 8 + ((l3 << 1) ^ (((nr >> 2) & 3) << 1))];
        }
        #pragma unroll
        for (int mt = 0; mt < 4; mt++)
            #pragma unroll
            for (int nt = 0; nt < 4; nt++)
                mma_fp16(acc[mt][nt], alo[mt].x, ahi[mt].x, alo[mt].y, ahi[mt].y,
                         bfr[nt].x, bfr[nt].y);
        if (t + 1 < T) {
            unsigned* dstp = (isB ? Bs[(t + 1) & 1] : As[(t + 1) & 1]) + lr * 8;
            *(uint2*)&dstp[0 ^ sw] = make_uint2(h2pack(f0.x, f0.y), h2pack(f2.x, f2.y));
            *(uint2*)&dstp[2 ^ sw] = make_uint2(h2pack(f0.z, f0.w), h2pack(f2.z, f2.w));
            *(uint2*)&dstp[4 ^ sw] = make_uint2(h2pack(f1.x, f1.y), h2pack(f3.x, f3.y));
            *(uint2*)&dstp[6 ^ sw] = make_uint2(h2pack(f1.z, f1.w), h2pack(f3.z, f3.w));
            __syncthreads();
        }
    }
    #pragma unroll
    for (int mt = 0; mt < 4; mt++) {
        const int row = bm + wm + mt * 16 + r8;
        #pragma unroll
        for (int nt = 0; nt < 4; nt++) {
            const int col = bn + wn + nt * 8 + (l3 << 1);
            const float bx = bias[col], by = bias[col + 1];
            float v0 = acc[mt][nt][0] + bx, v1 = acc[mt][nt][1] + by;
            float v2 = acc[mt][nt][2] + bx, v3 = acc[mt][nt][3] + by;
            if (relu) {
                v0 = fmaxf(v0, 0.f); v1 = fmaxf(v1, 0.f);
                v2 = fmaxf(v2, 0.f); v3 = fmaxf(v3, 0.f);
            }
            float2 w0 = {v0, v1}, w1 = {v2, v3};
            *(float2*)&C[(size_t)row * ldc + col]       = w0;
            *(float2*)&C[(size_t)(row + 8) * ldc + col] = w1;
        }
    }
}

// ---------------------------------------------------------------------------
// Fused flash attention: per (128-q tile, window-head), online softmax.
// grid = (7, 96), block 256 (8 warps 4m x 2n). Dynamic SMEM = FA_BYTES.
// ---------------------------------------------------------------------------
__global__ __launch_bounds__(256) void flash_attn(
    const float* __restrict__ qkv, float* __restrict__ attn, int shifted)
{
    extern __shared__ unsigned sm[];
    unsigned* Qs = sm + FA_QS;
    unsigned* Ps = sm + FA_PS;
    unsigned* KV = sm + FA_KV;
    float* redM = (float*)(sm + FA_REDM);
    float* redL = (float*)(sm + FA_REDL);

    const int wh = blockIdx.y, w = wh >> 3, h = wh & 7;
    const int bm = blockIdx.x << 7;
    const int tid = threadIdx.x, lane = tid & 31, wid = tid >> 5;
    const int wm = (wid & 3) << 5, wn = (wid >> 2) << 5;
    const int wnIdx = wid >> 2;
    const int r8 = lane >> 2, l3 = lane & 3;
    const float* base = qkv + (size_t)w * Ss * QKVLD + h * HDd;
    const float4 z4 = {0.f, 0.f, 0.f, 0.f};
    const bool maskw = (shifted != 0) && ((w % NWw) == 0);

    // Load Q tile [128 x 64] into Qs (tf32, stride QPST)
    {
        const int cc = (tid & 3) << 2;
        #pragma unroll
        for (int i = 0; i < 2; i++) {
            const int r = (tid >> 2) + (i << 6);
            const int q = bm + r;
            const float* p = base + (size_t)q * QKVLD + cc;
            #pragma unroll
            for (int j = 0; j < 4; j++) {
                float4 v = (q < Ss) ? *(const float4*)(p + 16 * j) : z4;
                *(uint4*)&Qs[r * QPST + cc + 16 * j] = tf4(v);
            }
        }
    }

    float accO[2][4][4] = {};
    float mst[2][2] = {{-1e30f, -1e30f}, {-1e30f, -1e30f}};
    float lst[2][2] = {{0.f, 0.f}, {0.f, 0.f}};

    for (int kt = 0; kt < 13; kt++) {
        const int k0 = kt << 6;
        __syncthreads();   // protect KV + Ps from previous iteration's MMA reads
        // Load K tile [64 x 64] -> KV (stride QPST)
        {
            const int kr = tid >> 2, cc = (tid & 3) << 2;
            const int gk = k0 + kr;
            const float* p = base + Dd + (size_t)gk * QKVLD + cc;
            #pragma unroll
            for (int j = 0; j < 4; j++) {
                float4 v = (gk < Ss) ? *(const float4*)(p + 16 * j) : z4;
                *(uint4*)&KV[kr * QPST + cc + 16 * j] = tf4(v);
            }
        }
        __syncthreads();

        // S = Q @ K^T
        float s[2][4][4] = {};
        #pragma unroll
        for (int kk = 0; kk < 64; kk += 8) {
            unsigned af[2][4], bf[4][2];
            const int c = kk + l3;
            #pragma unroll
            for (int mt = 0; mt < 2; mt++) {
                const int r = wm + mt * 16 + r8;
                af[mt][0] = Qs[r * QPST + c];
                af[mt][1] = Qs[(r + 8) * QPST + c];
                af[mt][2] = Qs[r * QPST + c + 4];
                af[mt][3] = Qs[(r + 8) * QPST + c + 4];
            }
            #pragma unroll
            for (int nt = 0; nt < 4; nt++) {
                const int n = wn + nt * 8 + r8;
                bf[nt][0] = KV[n * QPST + c];
                bf[nt][1] = KV[n * QPST + c + 4];
            }
            #pragma unroll
            for (int mt = 0; mt < 2; mt++)
                #pragma unroll
                for (int nt = 0; nt < 4; nt++)
                    mma_tf32(s[mt][nt], af[mt][0], af[mt][1], af[mt][2], af[mt][3],
                             bf[nt][0], bf[nt][1]);
        }

        // scale + mask + OOB; local row max
        float lm[2][2] = {{-1e30f, -1e30f}, {-1e30f, -1e30f}};
        #pragma unroll
        for (int mt = 0; mt < 2; mt++) {
            #pragma unroll
            for (int e = 0; e < 4; e++) {
                const int eh = e >> 1;
                const int q = bm + wm + mt * 16 + r8 + eh * 8;
                const int tq = q / FQn;
                #pragma unroll
                for (int nt = 0; nt < 4; nt++) {
                    const int k = k0 + wn + nt * 8 + (l3 << 1) + (e & 1);
                    float v = s[mt][nt][e] * 0.125f;
                    if (maskw) {
                        const int tk = k / FQn;
                        if ((tq < HALFh) != (tk < HALFh)) v -= 1000.0f;
                    }
                    if (k >= Ss) v = -1e30f;
                    s[mt][nt][e] = v;
                    lm[mt][eh] = fmaxf(lm[mt][eh], v);
                }
            }
        }
        // reduce max across lane&3 quad, publish per-warp-col
        #pragma unroll
        for (int mt = 0; mt < 2; mt++)
            #pragma unroll
            for (int eh = 0; eh < 2; eh++) {
                float v = lm[mt][eh];
                v = fmaxf(v, __shfl_xor_sync(0xffffffffu, v, 1));
                v = fmaxf(v, __shfl_xor_sync(0xffffffffu, v, 2));
                lm[mt][eh] = v;
                redM[wnIdx * 128 + wm + mt * 16 + eh * 8 + r8] = v;
            }
        __syncthreads();

        // m_new, alpha, p, local sums; store P; load V; rescale O
        float ls[2][2];
        float mnew[2][2];
        #pragma unroll
        for (int mt = 0; mt < 2; mt++) {
            #pragma unroll
            for (int eh = 0; eh < 2; eh++) {
                const int r = wm + mt * 16 + eh * 8 + r8;
                const float comb = fmaxf(redM[r], redM[128 + r]);
                const float mn = fmaxf(mst[mt][eh], comb);
                mnew[mt][eh] = mn;
                const float alpha = __expf(mst[mt][eh] - mn);
                mst[mt][eh] = mn;
                #pragma unroll
                for (int nt = 0; nt < 4; nt++) {
                    accO[mt][nt][eh * 2]     *= alpha;
                    accO[mt][nt][eh * 2 + 1] *= alpha;
                }
                lst[mt][eh] *= alpha;
                ls[mt][eh] = 0.f;
            }
        }
        #pragma unroll
        for (int mt = 0; mt < 2; mt++) {
            #pragma unroll
            for (int eh = 0; eh < 2; eh++) {
                const int r = wm + mt * 16 + eh * 8 + r8;
                #pragma unroll
                for (int nt = 0; nt < 4; nt++) {
                    const float p0 = __expf(s[mt][nt][eh * 2]     - mnew[mt][eh]);
                    const float p1 = __expf(s[mt][nt][eh * 2 + 1] - mnew[mt][eh]);
                    ls[mt][eh] += p0 + p1;
                    uint2 pp = {f2tf(p0), f2tf(p1)};
                    *(uint2*)&Ps[r * QPST + wn + nt * 8 + (l3 << 1)] = pp;
                }
                float v = ls[mt][eh];
                v += __shfl_xor_sync(0xffffffffu, v, 1);
                v += __shfl_xor_sync(0xffffffffu, v, 2);
                redL[wnIdx * 128 + r] = v;
            }
        }
        // Load V tile [64 x 64] -> KV k-major (stride VST); S-MMA reads done
        {
            const int vk = tid >> 2, cc = (tid & 3) << 2;
            const int gk = k0 + vk;
            const float* p = base + 2 * Dd + (size_t)gk * QKVLD + cc;
            #pragma unroll
            for (int j = 0; j < 4; j++) {
                float4 v = (gk < Ss) ? *(const float4*)(p + 16 * j) : z4;
                *(uint4*)&KV[vk * VST + cc + 16 * j] = tf4(v);
            }
        }
        __syncthreads();   // Ps, redL, V ready

        #pragma unroll
        for (int mt = 0; mt < 2; mt++)
            #pragma unroll
            for (int eh = 0; eh < 2; eh++) {
                const int r = wm + mt * 16 + eh * 8 + r8;
                lst[mt][eh] += redL[r] + redL[128 + r];
            }

        // O += P @ V
        #pragma unroll
        for (int kk = 0; kk < 64; kk += 8) {
            unsigned af[2][4], bf[4][2];
            const int c = kk + l3;
            #pragma unroll
            for (int mt = 0; mt < 2; mt++) {
                const int r = wm + mt * 16 + r8;
                af[mt][0] = Ps[r * QPST + c];
                af[mt][1] = Ps[(r + 8) * QPST + c];
                af[mt][2] = Ps[r * QPST + c + 4];
                af[mt][3] = Ps[(r + 8) * QPST + c + 4];
            }
            #pragma unroll
            for (int nt = 0; nt < 4; nt++) {
                const int n = wn + nt * 8 + r8;
                bf[nt][0] = KV[c * VST + n];
                bf[nt][1] = KV[(c + 4) * VST + n];
            }
            #pragma unroll
            for (int mt = 0; mt < 2; mt++)
                #pragma unroll
                for (int nt = 0; nt < 4; nt++)
                    mma_tf32(accO[mt][nt], af[mt][0], af[mt][1], af[mt][2], af[mt][3],
                             bf[nt][0], bf[nt][1]);
        }
    }

    // Epilogue: O /= l, store to attn
    #pragma unroll
    for (int mt = 0; mt < 2; mt++) {
        #pragma unroll
        for (int eh = 0; eh < 2; eh++) {
            const int q = bm + wm + mt * 16 + eh * 8 + r8;
            if (q >= Ss) continue;
            const float inv = 1.0f / lst[mt][eh];
            #pragma unroll
            for (int nt = 0; nt < 4; nt++) {
                const int col = wn + nt * 8 + (l3 << 1);
                float2 o2 = {accO[mt][nt][eh * 2] * inv, accO[mt][nt][eh * 2 + 1] * inv};
                *(float2*)&attn[(size_t)(w * Ss + q) * Dd + h * HDd + col] = o2;
            }
        }
    }
}

// ---------------------------------------------------------------------------
// Window gather with roll: xw[w*S+s] = x[token(w,s,shift)]
// ---------------------------------------------------------------------------
__global__ __launch_bounds__(256) void gather_win(
    const float* __restrict__ x, float* __restrict__ xw, int shift)
{
    const int idx = blockIdx.x * 256 + threadIdx.x;
    const int row = idx >> 7;
    const int c = idx & 127;
    const int w = row / Ss, sidx = row % Ss;
    const int b = w / NWw, nw = w % NWw;
    const int tl = sidx / FQn, fq = sidx % FQn;
    int t = nw * WSZw + tl - shift;
    if (t < 0) t += Tt;
    const size_t n = (size_t)(b * Tt + t) * FQn + fq;
    ((float4*)xw)[(size_t)row * 128 + c] = ((const float4*)x)[n * 128 + c];
}

// ---------------------------------------------------------------------------
// dst[row'] = LayerNorm(xa[row] + xb[row]) * gs + gb
// ---------------------------------------------------------------------------
__global__ __launch_bounds__(256) void add_ln(
    const float* __restrict__ xa, const float* __restrict__ xb,
    const float* __restrict__ gs, const float* __restrict__ gb,
    float* __restrict__ dst, int scatter, int shift)
{
    const int row = blockIdx.x;
    const int tid = threadIdx.x;
    const float* pa = xa + (size_t)row * Dd;
    const float* pb = xb + (size_t)row * Dd;
    const float v0 = pa[tid] + pb[tid];
    const float v1 = pa[tid + 256] + pb[tid + 256];
    __shared__ float red1[8];
    __shared__ float red2[8];
    float s = v0 + v1;
    #pragma unroll
    for (int o = 16; o > 0; o >>= 1) s += __shfl_xor_sync(0xffffffffu, s, o);
    if ((tid & 31) == 0) red1[tid >> 5] = s;
    __syncthreads();
    const float mu = (red1[0] + red1[1] + red1[2] + red1[3] +
                      red1[4] + red1[5] + red1[6] + red1[7]) * (1.0f / Dd);
    const float d0 = v0 - mu, d1 = v1 - mu;
    float ss = d0 * d0 + d1 * d1;
    #pragma unroll
    for (int o = 16; o > 0; o >>= 1) ss += __shfl_xor_sync(0xffffffffu, ss, o);
    if ((tid & 31) == 0) red2[tid >> 5] = ss;
    __syncthreads();
    const float var = (red2[0] + red2[1] + red2[2] + red2[3] +
                       red2[4] + red2[5] + red2[6] + red2[7]) * (1.0f / Dd);
    const float rstd = rsqrtf(var + 1e-5f);
    size_t drow = row;
    if (scatter) {
        const int w = row / Ss, sidx = row % Ss;
        const int b = w / NWw, nw = w % NWw;
        const int tl = sidx / FQn, fq = sidx % FQn;
        int t = nw * WSZw + tl - shift;
        if (t < 0) t += Tt;
        drow = (size_t)(b * Tt + t) * FQn + fq;
    }
    float* pd = dst + drow * Dd;
    pd[tid]       = d0 * rstd * gs[tid]       + gb[tid];
    pd[tid + 256] = d1 * rstd * gs[tid + 256] + gb[tid + 256];
}

// ---------------------------------------------------------------------------
extern "C" void kernel_launch(void* const* d_in, const int* in_sizes, int n_in,
                              void* d_out, int out_size)
{
    const float* fqin = (const float*)d_in[0];
    const float* Wp   = (const float*)d_in[1];
    const float* bp   = (const float*)d_in[2];
    const float* Wqkv = (const float*)d_in[3];
    const float* bqkv = (const float*)d_in[4];
    const float* Wo   = (const float*)d_in[5];
    const float* bo   = (const float*)d_in[6];
    const float* ln1s = (const float*)d_in[7];
    const float* ln1b = (const float*)d_in[8];
    const float* W1   = (const float*)d_in[9];
    const float* b1   = (const float*)d_in[10];
    const float* W2   = (const float*)d_in[11];
    const float* b2   = (const float*)d_in[12];
    const float* ln2s = (const float*)d_in[13];
    const float* ln2b = (const float*)d_in[14];
    float* out = (float*)d_out;

    float *x, *xw, *tmp, *attn, *qkv, *ffn;
    cudaGetSymbolAddress((void**)&x,    g_x);
    cudaGetSymbolAddress((void**)&xw,   g_xw);
    cudaGetSymbolAddress((void**)&tmp,  g_tmp);
    cudaGetSymbolAddress((void**)&attn, g_attn);
    cudaGetSymbolAddress((void**)&qkv,  g_qkv);
    cudaGetSymbolAddress((void**)&ffn,  g_ffn);

    cudaFuncSetAttribute(flash_attn,
                         cudaFuncAttributeMaxDynamicSharedMemorySize, FA_BYTES);

    // Input projection: x = fq @ Wp^T + bp
    gemm_tc<<<dim3(Dd / 128, NTOK / 128), 256>>>(fqin, Dd, Wp, Dd, bp, x, Dd, Dd, 0);

    for (int i = 0; i < Ll; i++) {
        const int shifted = i & 1;
        const int shift = shifted ? HALFh : 0;

        // window gather (with roll for shifted layers)
        gather_win<<<NTOK * 128 / 256, 256>>>(x, xw, shift);

        // QKV projection
        gemm_tc<<<dim3(3 * Dd / 128, NTOK / 128), 256>>>(
            xw, Dd, Wqkv + (size_t)i * 3 * Dd * Dd, Dd,
            bqkv + (size_t)i * 3 * Dd, qkv, 3 * Dd, Dd, 0);

        // fused attention (scores + mask + softmax + AV)
        flash_attn<<<dim3(7, WHn), 256, FA_BYTES>>>(qkv, attn, shifted);

        // output projection
        gemm_tc<<<dim3(Dd / 128, NTOK / 128), 256>>>(
            attn, Dd, Wo + (size_t)i * Dd * Dd, Dd,
            bo + (size_t)i * Dd, tmp, Dd, Dd, 0);

        // residual + LN1, scatter back (inverse roll)
        add_ln<<<NTOK, 256>>>(xw, tmp, ln1s + (size_t)i * Dd, ln1b + (size_t)i * Dd,
                              x, 1, shift);

        // FFN
        gemm_tc<<<dim3(DFFd / 128, NTOK / 128), 256>>>(
            x, Dd, W1 + (size_t)i * DFFd * Dd, Dd,
            b1 + (size_t)i * DFFd, ffn, DFFd, Dd, 1);
        gemm_tc<<<dim3(Dd / 128, NTOK / 128), 256>>>(
            ffn, DFFd, W2 + (size_t)i * Dd * DFFd, DFFd,
            b2 + (size_t)i * Dd, tmp, Dd, DFFd, 0);

        // residual + LN2 (final layer writes straight to d_out)
        add_ln<<<NTOK, 256>>>(x, tmp, ln2s + (size_t)i * Dd, ln2b + (size_t)i * Dd,
                              (i == Ll - 1) ? out : x, 0, 0);
    }
    (void)in_sizes; (void)n_in; (void)out_size;
}

// round 15
// speedup vs baseline: 1.0347x; 1.0347x over previous
#include <cuda_runtime.h>
#include <cuda_fp16.h>
#include <cstdint>

// Problem constants
#define Bb    2
#define Tt    48
#define FQn   100
#define Dd    512
#define Hh    8
#define HDd   64
#define DFFd  2048
#define Ll    6
#define WSZw  8
#define NWw   6          // windows per batch item (T/WSZ)
#define NWIN  12         // B * NWw
#define Ss    800        // WSZ * FQ
#define HALFh 4          // ceil(WSZ/2)
#define NTOK  9600       // B*T*FQ
#define WHn   96         // NWIN * H
#define QKVLD 1536       // 3*D row stride in qkv buffer

#define QPST 68          // SMEM stride for 64-wide q/k/p tiles (≡4 mod 32)
#define VST 72           // SMEM stride for k-major V tile (≡8 mod 32)

// Flash SMEM layout (words)
#define FA_QS   0
#define FA_PS   (128 * QPST)
#define FA_KV   (FA_PS + 128 * QPST)
#define FA_REDM (FA_KV + 64 * VST)
#define FA_REDL (FA_REDM + 256)
#define FA_WORDS (FA_REDL + 256)
#define FA_BYTES (FA_WORDS * 4)

// fp16 weight arena offsets (halves)
#define OWP   0
#define OWQKV 262144                      // D*D
#define OWO   (OWQKV + Ll * 3 * Dd * Dd)  // + 4718592
#define OW1   (OWO + Ll * Dd * Dd)        // + 1572864
#define OW2   (OW1 + Ll * DFFd * Dd)      // + 6291456
#define W16TOT (OW2 + Ll * Dd * DFFd)

// Scratch (device globals: allocation-guard safe)
__device__ float  g_x[NTOK * Dd];
__device__ float  g_xw[NTOK * Dd];
__device__ float  g_tmp[NTOK * Dd];
__device__ float  g_qkv[NTOK * 3 * Dd];
__device__ __half g_w16[W16TOT];
__device__ __half g_fq16[NTOK * Dd];
__device__ __half g_xw16[NTOK * Dd];
__device__ __half g_x16[NTOK * Dd];
__device__ __half g_ffn16[NTOK * DFFd];
__device__ __half g_attn16[NTOK * Dd];

// ---------------------------------------------------------------------------
// helpers
// ---------------------------------------------------------------------------
__device__ __forceinline__ unsigned f2tf(float f) {
    unsigned u;
    asm("cvt.rna.tf32.f32 %0, %1;" : "=r"(u) : "f"(f));
    return u;
}

__device__ __forceinline__ void mma_tf32(
    float c[4], unsigned a0, unsigned a1, unsigned a2, unsigned a3,
    unsigned b0, unsigned b1)
{
    asm volatile(
        "mma.sync.aligned.m16n8k8.row.col.f32.tf32.tf32.f32 "
        "{%0,%1,%2,%3}, {%4,%5,%6,%7}, {%8,%9}, {%0,%1,%2,%3};"
        : "+f"(c[0]), "+f"(c[1]), "+f"(c[2]), "+f"(c[3])
        : "r"(a0), "r"(a1), "r"(a2), "r"(a3), "r"(b0), "r"(b1));
}

__device__ __forceinline__ void mma_fp16(
    float c[4], unsigned a0, unsigned a1, unsigned a2, unsigned a3,
    unsigned b0, unsigned b1)
{
    asm volatile(
        "mma.sync.aligned.m16n8k16.row.col.f32.f16.f16.f32 "
        "{%0,%1,%2,%3}, {%4,%5,%6,%7}, {%8,%9}, {%0,%1,%2,%3};"
        : "+f"(c[0]), "+f"(c[1]), "+f"(c[2]), "+f"(c[3])
        : "r"(a0), "r"(a1), "r"(a2), "r"(a3), "r"(b0), "r"(b1));
}

__device__ __forceinline__ uint4 tf4(float4 v) {
    return make_uint4(f2tf(v.x), f2tf(v.y), f2tf(v.z), f2tf(v.w));
}

// ---------------------------------------------------------------------------
// fp32 -> fp16 conversion (n % 4 == 0)
// ---------------------------------------------------------------------------
__global__ __launch_bounds__(256) void cvt_f2h(
    const float* __restrict__ s, __half* __restrict__ d, int n)
{
    const int i = (blockIdx.x * 256 + threadIdx.x) * 4;
    if (i >= n) return;
    float4 v = *(const float4*)(s + i);
    __half2 h0 = __floats2half2_rn(v.x, v.y);
    __half2 h1 = __floats2half2_rn(v.z, v.w);
    *(__half2*)(d + i)     = h0;
    *(__half2*)(d + i + 2) = h1;
}

// ---------------------------------------------------------------------------
// fp16 tensor-core NT GEMM with cp.async 4-stage pipeline.
// C[N,M] = A[N,K] @ B[M,K]^T + bias[M]; A,B fp16 row-major, C fp32 or fp16.
// Block 256 thr = 8 warps (2m x 4n), tile 128x128, K-tile 16.
// SMEM row = 16 halves (8 words); chunk swizzle: 16B chunk ^= (row>>2)&1.
// grid = (M/128, rows/128); rows%128==0, M%128==0, K%16==0, K>=64.
// ---------------------------------------------------------------------------
__global__ __launch_bounds__(256) void gemm_tc(
    const __half* __restrict__ A, int lda,
    const __half* __restrict__ B, int ldb,
    const float* __restrict__ bias,
    void* __restrict__ Cv, int ldc,
    int K, int relu, int out16)
{
    __shared__ unsigned Ash[4][128 * 8];
    __shared__ unsigned Bsh[4][128 * 8];
    const int tid = threadIdx.x, lane = tid & 31, wid = tid >> 5;
    const int wm = (wid & 1) << 6, wn = (wid >> 1) << 5;
    const int bm = blockIdx.y << 7, bn = blockIdx.x << 7;
    const int r8 = lane >> 2, l3 = lane & 3;
    const int row = tid >> 1, ch = tid & 1;
    const int pr = (row >> 2) & 1;
    const unsigned dstoff = row * 8 + ((ch ^ pr) << 2);   // words
    const __half* srcA = A + (size_t)(bm + row) * lda + (ch << 3);
    const __half* srcB = B + (size_t)(bn + row) * ldb + (ch << 3);
    float acc[4][4][4] = {};
    const int T = K >> 4;

    #define ISSUE_STAGE(t) do {                                                \
        const int s_ = (t) & 3;                                                \
        unsigned da_ = (unsigned)__cvta_generic_to_shared(&Ash[s_][dstoff]);   \
        unsigned db_ = (unsigned)__cvta_generic_to_shared(&Bsh[s_][dstoff]);   \
        asm volatile("cp.async.cg.shared.global [%0], [%1], 16;\n"             \
                     :: "r"(da_), "l"(srcA + (t) * 16) : "memory");            \
        asm volatile("cp.async.cg.shared.global [%0], [%1], 16;\n"             \
                     :: "r"(db_), "l"(srcB + (t) * 16) : "memory");            \
    } while (0)

    ISSUE_STAGE(0); asm volatile("cp.async.commit_group;\n" ::: "memory");
    ISSUE_STAGE(1); asm volatile("cp.async.commit_group;\n" ::: "memory");
    ISSUE_STAGE(2); asm volatile("cp.async.commit_group;\n" ::: "memory");

    const int w0 = l3 ^ (((r8 >> 2) & 1) << 2);
    for (int t = 0; t < T; t++) {
        asm volatile("cp.async.wait_group 2;\n" ::: "memory");
        __syncthreads();
        if (t + 3 < T) ISSUE_STAGE(t + 3);
        asm volatile("cp.async.commit_group;\n" ::: "memory");
        const unsigned* Ab = Ash[t & 3];
        const unsigned* Bbf = Bsh[t & 3];
        unsigned a0[4], a1[4], a2[4], a3[4], b0[4], b1[4];
        #pragma unroll
        for (int mt = 0; mt < 4; mt++) {
            const int r = wm + mt * 16 + r8;
            a0[mt] = Ab[r * 8 + w0];
            a2[mt] = Ab[r * 8 + (w0 ^ 4)];
            a1[mt] = Ab[(r + 8) * 8 + w0];
            a3[mt] = Ab[(r + 8) * 8 + (w0 ^ 4)];
        }
        #pragma unroll
        for (int nt = 0; nt < 4; nt++) {
            const int n = wn + nt * 8 + r8;
            b0[nt] = Bbf[n * 8 + w0];
            b1[nt] = Bbf[n * 8 + (w0 ^ 4)];
        }
        #pragma unroll
        for (int mt = 0; mt < 4; mt++)
            #pragma unroll
            for (int nt = 0; nt < 4; nt++)
                mma_fp16(acc[mt][nt], a0[mt], a1[mt], a2[mt], a3[mt],
                         b0[nt], b1[nt]);
    }
    #undef ISSUE_STAGE

    #pragma unroll
    for (int mt = 0; mt < 4; mt++) {
        const int crow = bm + wm + mt * 16 + r8;
        #pragma unroll
        for (int nt = 0; nt < 4; nt++) {
            const int col = bn + wn + nt * 8 + (l3 << 1);
            const float bx = bias[col], by = bias[col + 1];
            float v0 = acc[mt][nt][0] + bx, v1 = acc[mt][nt][1] + by;
            float v2 = acc[mt][nt][2] + bx, v3 = acc[mt][nt][3] + by;
            if (relu) {
                v0 = fmaxf(v0, 0.f); v1 = fmaxf(v1, 0.f);
                v2 = fmaxf(v2, 0.f); v3 = fmaxf(v3, 0.f);
            }
            if (out16) {
                __half* C16 = (__half*)Cv;
                *(__half2*)&C16[(size_t)crow * ldc + col]       = __floats2half2_rn(v0, v1);
                *(__half2*)&C16[(size_t)(crow + 8) * ldc + col] = __floats2half2_rn(v2, v3);
            } else {
                float* C = (float*)Cv;
                float2 q0 = {v0, v1}, q1 = {v2, v3};
                *(float2*)&C[(size_t)crow * ldc + col]       = q0;
                *(float2*)&C[(size_t)(crow + 8) * ldc + col] = q1;
            }
        }
    }
}

// ---------------------------------------------------------------------------
// Fused flash attention: per (128-q tile, window-head), online softmax.
// grid = (7, 96), block 256 (8 warps 4m x 2n). Dynamic SMEM = FA_BYTES.
// Writes fp16 attention output (consumed by Oproj GEMM).
// ---------------------------------------------------------------------------
__global__ __launch_bounds__(256) void flash_attn(
    const float* __restrict__ qkv, __half* __restrict__ attn16, int shifted)
{
    extern __shared__ unsigned sm[];
    unsigned* Qs = sm + FA_QS;
    unsigned* Ps = sm + FA_PS;
    unsigned* KV = sm + FA_KV;
    float* redM = (float*)(sm + FA_REDM);
    float* redL = (float*)(sm + FA_REDL);

    const int wh = blockIdx.y, w = wh >> 3, h = wh & 7;
    const int bm = blockIdx.x << 7;
    const int tid = threadIdx.x, lane = tid & 31, wid = tid >> 5;
    const int wm = (wid & 3) << 5, wn = (wid >> 2) << 5;
    const int wnIdx = wid >> 2;
    const int r8 = lane >> 2, l3 = lane & 3;
    const float* base = qkv + (size_t)w * Ss * QKVLD + h * HDd;
    const float4 z4 = {0.f, 0.f, 0.f, 0.f};
    const bool maskw = (shifted != 0) && ((w % NWw) == 0);

    // Load Q tile [128 x 64] into Qs (tf32, stride QPST)
    {
        const int cc = (tid & 3) << 2;
        #pragma unroll
        for (int i = 0; i < 2; i++) {
            const int r = (tid >> 2) + (i << 6);
            const int q = bm + r;
            const float* p = base + (size_t)q * QKVLD + cc;
            #pragma unroll
            for (int j = 0; j < 4; j++) {
                float4 v = (q < Ss) ? *(const float4*)(p + 16 * j) : z4;
                *(uint4*)&Qs[r * QPST + cc + 16 * j] = tf4(v);
            }
        }
    }

    float accO[2][4][4] = {};
    float mst[2][2] = {{-1e30f, -1e30f}, {-1e30f, -1e30f}};
    float lst[2][2] = {{0.f, 0.f}, {0.f, 0.f}};

    for (int kt = 0; kt < 13; kt++) {
        const int k0 = kt << 6;
        __syncthreads();
        // Load K tile [64 x 64] -> KV (stride QPST)
        {
            const int kr = tid >> 2, cc = (tid & 3) << 2;
            const int gk = k0 + kr;
            const float* p = base + Dd + (size_t)gk * QKVLD + cc;
            #pragma unroll
            for (int j = 0; j < 4; j++) {
                float4 v = (gk < Ss) ? *(const float4*)(p + 16 * j) : z4;
                *(uint4*)&KV[kr * QPST + cc + 16 * j] = tf4(v);
            }
        }
        __syncthreads();

        // S = Q @ K^T
        float s[2][4][4] = {};
        #pragma unroll
        for (int kk = 0; kk < 64; kk += 8) {
            unsigned af[2][4], bf[4][2];
            const int c = kk + l3;
            #pragma unroll
            for (int mt = 0; mt < 2; mt++) {
                const int r = wm + mt * 16 + r8;
                af[mt][0] = Qs[r * QPST + c];
                af[mt][1] = Qs[(r + 8) * QPST + c];
                af[mt][2] = Qs[r * QPST + c + 4];
                af[mt][3] = Qs[(r + 8) * QPST + c + 4];
            }
            #pragma unroll
            for (int nt = 0; nt < 4; nt++) {
                const int n = wn + nt * 8 + r8;
                bf[nt][0] = KV[n * QPST + c];
                bf[nt][1] = KV[n * QPST + c + 4];
            }
            #pragma unroll
            for (int mt = 0; mt < 2; mt++)
                #pragma unroll
                for (int nt = 0; nt < 4; nt++)
                    mma_tf32(s[mt][nt], af[mt][0], af[mt][1], af[mt][2], af[mt][3],
                             bf[nt][0], bf[nt][1]);
        }

        // scale + mask + OOB; local row max
        float lm[2][2] = {{-1e30f, -1e30f}, {-1e30f, -1e30f}};
        #pragma unroll
        for (int mt = 0; mt < 2; mt++) {
            #pragma unroll
            for (int e = 0; e < 4; e++) {
                const int eh = e >> 1;
                const int q = bm + wm + mt * 16 + r8 + eh * 8;
                const int tq = q / FQn;
                #pragma unroll
                for (int nt = 0; nt < 4; nt++) {
                    const int k = k0 + wn + nt * 8 + (l3 << 1) + (e & 1);
                    float v = s[mt][nt][e] * 0.125f;
                    if (maskw) {
                        const int tk = k / FQn;
                        if ((tq < HALFh) != (tk < HALFh)) v -= 1000.0f;
                    }
                    if (k >= Ss) v = -1e30f;
                    s[mt][nt][e] = v;
                    lm[mt][eh] = fmaxf(lm[mt][eh], v);
                }
            }
        }
        #pragma unroll
        for (int mt = 0; mt < 2; mt++)
            #pragma unroll
            for (int eh = 0; eh < 2; eh++) {
                float v = lm[mt][eh];
                v = fmaxf(v, __shfl_xor_sync(0xffffffffu, v, 1));
                v = fmaxf(v, __shfl_xor_sync(0xffffffffu, v, 2));
                lm[mt][eh] = v;
                redM[wnIdx * 128 + wm + mt * 16 + eh * 8 + r8] = v;
            }
        __syncthreads();

        float ls[2][2];
        float mnew[2][2];
        #pragma unroll
        for (int mt = 0; mt < 2; mt++) {
            #pragma unroll
            for (int eh = 0; eh < 2; eh++) {
                const int r = wm + mt * 16 + eh * 8 + r8;
                const float comb = fmaxf(redM[r], redM[128 + r]);
                const float mn = fmaxf(mst[mt][eh], comb);
                mnew[mt][eh] = mn;
                const float alpha = __expf(mst[mt][eh] - mn);
                mst[mt][eh] = mn;
                #pragma unroll
                for (int nt = 0; nt < 4; nt++) {
                    accO[mt][nt][eh * 2]     *= alpha;
                    accO[mt][nt][eh * 2 + 1] *= alpha;
                }
                lst[mt][eh] *= alpha;
                ls[mt][eh] = 0.f;
            }
        }
        #pragma unroll
        for (int mt = 0; mt < 2; mt++) {
            #pragma unroll
            for (int eh = 0; eh < 2; eh++) {
                const int r = wm + mt * 16 + eh * 8 + r8;
                #pragma unroll
                for (int nt = 0; nt < 4; nt++) {
                    const float p0 = __expf(s[mt][nt][eh * 2]     - mnew[mt][eh]);
                    const float p1 = __expf(s[mt][nt][eh * 2 + 1] - mnew[mt][eh]);
                    ls[mt][eh] += p0 + p1;
                    uint2 pp = {f2tf(p0), f2tf(p1)};
                    *(uint2*)&Ps[r * QPST + wn + nt * 8 + (l3 << 1)] = pp;
                }
                float v = ls[mt][eh];
                v += __shfl_xor_sync(0xffffffffu, v, 1);
                v += __shfl_xor_sync(0xffffffffu, v, 2);
                redL[wnIdx * 128 + r] = v;
            }
        }
        // Load V tile [64 x 64] -> KV k-major (stride VST)
        {
            const int vk = tid >> 2, cc = (tid & 3) << 2;
            const int gk = k0 + vk;
            const float* p = base + 2 * Dd + (size_t)gk * QKVLD + cc;
            #pragma unroll
            for (int j = 0; j < 4; j++) {
                float4 v = (gk < Ss) ? *(const float4*)(p + 16 * j) : z4;
                *(uint4*)&KV[vk * VST + cc + 16 * j] = tf4(v);
            }
        }
        __syncthreads();

        #pragma unroll
        for (int mt = 0; mt < 2; mt++)
            #pragma unroll
            for (int eh = 0; eh < 2; eh++) {
                const int r = wm + mt * 16 + eh * 8 + r8;
                lst[mt][eh] += redL[r] + redL[128 + r];
            }

        // O += P @ V
        #pragma unroll
        for (int kk = 0; kk < 64; kk += 8) {
            unsigned af[2][4], bf[4][2];
            const int c = kk + l3;
            #pragma unroll
            for (int mt = 0; mt < 2; mt++) {
                const int r = wm + mt * 16 + r8;
                af[mt][0] = Ps[r * QPST + c];
                af[mt][1] = Ps[(r + 8) * QPST + c];
                af[mt][2] = Ps[r * QPST + c + 4];
                af[mt][3] = Ps[(r + 8) * QPST + c + 4];
            }
            #pragma unroll
            for (int nt = 0; nt < 4; nt++) {
                const int n = wn + nt * 8 + r8;
                bf[nt][0] = KV[c * VST + n];
                bf[nt][1] = KV[(c + 4) * VST + n];
            }
            #pragma unroll
            for (int mt = 0; mt < 2; mt++)
                #pragma unroll
                for (int nt = 0; nt < 4; nt++)
                    mma_tf32(accO[mt][nt], af[mt][0], af[mt][1], af[mt][2], af[mt][3],
                             bf[nt][0], bf[nt][1]);
        }
    }

    // Epilogue: O /= l, fp16 store
    #pragma unroll
    for (int mt = 0; mt < 2; mt++) {
        #pragma unroll
        for (int eh = 0; eh < 2; eh++) {
            const int q = bm + wm + mt * 16 + eh * 8 + r8;
            if (q >= Ss) continue;
            const float inv = 1.0f / lst[mt][eh];
            #pragma unroll
            for (int nt = 0; nt < 4; nt++) {
                const int col = wn + nt * 8 + (l3 << 1);
                *(__half2*)&attn16[(size_t)(w * Ss + q) * Dd + h * HDd + col] =
                    __floats2half2_rn(accO[mt][nt][eh * 2] * inv,
                                      accO[mt][nt][eh * 2 + 1] * inv);
            }
        }
    }
}

// ---------------------------------------------------------------------------
// Window gather with roll: xw[w*S+s] = x[token(w,s,shift)]; fp32 + fp16 out.
// ---------------------------------------------------------------------------
__global__ __launch_bounds__(256) void gather_win(
    const float* __restrict__ x, float* __restrict__ xw,
    __half* __restrict__ xw16, int shift)
{
    const int idx = blockIdx.x * 256 + threadIdx.x;
    const int row = idx >> 7;
    const int c = idx & 127;
    const int w = row / Ss, sidx = row % Ss;
    const int b = w / NWw, nw = w % NWw;
    const int tl = sidx / FQn, fq = sidx % FQn;
    int t = nw * WSZw + tl - shift;
    if (t < 0) t += Tt;
    const size_t n = (size_t)(b * Tt + t) * FQn + fq;
    float4 v = ((const float4*)x)[n * 128 + c];
    ((float4*)xw)[(size_t)row * 128 + c] = v;
    __half2 h0 = __floats2half2_rn(v.x, v.y);
    __half2 h1 = __floats2half2_rn(v.z, v.w);
    __half* p16 = xw16 + (size_t)row * Dd + (c << 2);
    *(__half2*)p16       = h0;
    *(__half2*)(p16 + 2) = h1;
}

// ---------------------------------------------------------------------------
// dst[row'] = LayerNorm(xa[row] + xb[row]) * gs + gb  (+ optional fp16 copy)
// ---------------------------------------------------------------------------
__global__ __launch_bounds__(256) void add_ln(
    const float* __restrict__ xa, const float* __restrict__ xb,
    const float* __restrict__ gs, const float* __restrict__ gb,
    float* __restrict__ dst, __half* __restrict__ dst16,
    int scatter, int shift)
{
    const int row = blockIdx.x;
    const int tid = threadIdx.x;
    const float* pa = xa + (size_t)row * Dd;
    const float* pb = xb + (size_t)row * Dd;
    const float v0 = pa[tid] + pb[tid];
    const float v1 = pa[tid + 256] + pb[tid + 256];
    __shared__ float red1[8];
    __shared__ float red2[8];
    float s = v0 + v1;
    #pragma unroll
    for (int o = 16; o > 0; o >>= 1) s += __shfl_xor_sync(0xffffffffu, s, o);
    if ((tid & 31) == 0) red1[tid >> 5] = s;
    __syncthreads();
    const float mu = (red1[0] + red1[1] + red1[2] + red1[3] +
                      red1[4] + red1[5] + red1[6] + red1[7]) * (1.0f / Dd);
    const float d0 = v0 - mu, d1 = v1 - mu;
    float ss = d0 * d0 + d1 * d1;
    #pragma unroll
    for (int o = 16; o > 0; o >>= 1) ss += __shfl_xor_sync(0xffffffffu, ss, o);
    if ((tid & 31) == 0) red2[tid >> 5] = ss;
    __syncthreads();
    const float var = (red2[0] + red2[1] + red2[2] + red2[3] +
                       red2[4] + red2[5] + red2[6] + red2[7]) * (1.0f / Dd);
    const float rstd = rsqrtf(var + 1e-5f);
    size_t drow = row;
    if (scatter) {
        const int w = row / Ss, sidx = row % Ss;
        const int b = w / NWw, nw = w % NWw;
        const int tl = sidx / FQn, fq = sidx % FQn;
        int t = nw * WSZw + tl - shift;
        if (t < 0) t += Tt;
        drow = (size_t)(b * Tt + t) * FQn + fq;
    }
    const float o0 = d0 * rstd * gs[tid]       + gb[tid];
    const float o1 = d1 * rstd * gs[tid + 256] + gb[tid + 256];
    float* pd = dst + drow * Dd;
    pd[tid]       = o0;
    pd[tid + 256] = o1;
    if (dst16) {
        __half* ph = dst16 + drow * Dd;
        ph[tid]       = __float2half_rn(o0);
        ph[tid + 256] = __float2half_rn(o1);
    }
}

// ---------------------------------------------------------------------------
extern "C" void kernel_launch(void* const* d_in, const int* in_sizes, int n_in,
                              void* d_out, int out_size)
{
    const float* fqin = (const float*)d_in[0];
    const float* Wp   = (const float*)d_in[1];
    const float* bp   = (const float*)d_in[2];
    const float* Wqkv = (const float*)d_in[3];
    const float* bqkv = (const float*)d_in[4];
    const float* Wo   = (const float*)d_in[5];
    const float* bo   = (const float*)d_in[6];
    const float* ln1s = (const float*)d_in[7];
    const float* ln1b = (const float*)d_in[8];
    const float* W1   = (const float*)d_in[9];
    const float* b1   = (const float*)d_in[10];
    const float* W2   = (const float*)d_in[11];
    const float* b2   = (const float*)d_in[12];
    const float* ln2s = (const float*)d_in[13];
    const float* ln2b = (const float*)d_in[14];
    float* out = (float*)d_out;

    float *x, *xw, *tmp, *qkv;
    __half *w16, *fq16, *xw16, *x16, *ffn16, *attn16;
    cudaGetSymbolAddress((void**)&x,     g_x);
    cudaGetSymbolAddress((void**)&xw,    g_xw);
    cudaGetSymbolAddress((void**)&tmp,   g_tmp);
    cudaGetSymbolAddress((void**)&qkv,   g_qkv);
    cudaGetSymbolAddress((void**)&w16,   g_w16);
    cudaGetSymbolAddress((void**)&fq16,  g_fq16);
    cudaGetSymbolAddress((void**)&xw16,  g_xw16);
    cudaGetSymbolAddress((void**)&x16,   g_x16);
    cudaGetSymbolAddress((void**)&ffn16, g_ffn16);
    cudaGetSymbolAddress((void**)&attn16, g_attn16);

    cudaFuncSetAttribute(flash_attn,
                         cudaFuncAttributeMaxDynamicSharedMemorySize, FA_BYTES);

    // Convert weights + input to fp16 (every call; deterministic)
    #define CVT(src, dst, n) cvt_f2h<<<((n) / 4 + 255) / 256, 256>>>(src, dst, n)
    CVT(Wp,   w16 + OWP,   Dd * Dd);
    CVT(Wqkv, w16 + OWQKV, Ll * 3 * Dd * Dd);
    CVT(Wo,   w16 + OWO,   Ll * Dd * Dd);
    CVT(W1,   w16 + OW1,   Ll * DFFd * Dd);
    CVT(W2,   w16 + OW2,   Ll * Dd * DFFd);
    CVT(fqin, fq16,        NTOK * Dd);
    #undef CVT

    // Input projection: x = fq @ Wp^T + bp
    gemm_tc<<<dim3(Dd / 128, NTOK / 128), 256>>>(
        fq16, Dd, w16 + OWP, Dd, bp, x, Dd, Dd, 0, 0);

    for (int i = 0; i < Ll; i++) {
        const int shifted = i & 1;
        const int shift = shifted ? HALFh : 0;

        // window gather (with roll for shifted layers), fp32 + fp16
        gather_win<<<NTOK * 128 / 256, 256>>>(x, xw, xw16, shift);

        // QKV projection (A fp16, C fp32)
        gemm_tc<<<dim3(3 * Dd / 128, NTOK / 128), 256>>>(
            xw16, Dd, w16 + OWQKV + (size_t)i * 3 * Dd * Dd, Dd,
            bqkv + (size_t)i * 3 * Dd, qkv, 3 * Dd, Dd, 0, 0);

        // fused attention -> fp16 output
        flash_attn<<<dim3(7, WHn), 256, FA_BYTES>>>(qkv, attn16, shifted);

        // output projection
        gemm_tc<<<dim3(Dd / 128, NTOK / 128), 256>>>(
            attn16, Dd, w16 + OWO + (size_t)i * Dd * Dd, Dd,
            bo + (size_t)i * Dd, tmp, Dd, Dd, 0, 0);

        // residual + LN1, scatter back; also write fp16 for FFN1
        add_ln<<<NTOK, 256>>>(xw, tmp, ln1s + (size_t)i * Dd, ln1b + (size_t)i * Dd,
                              x, x16, 1, shift);

        // FFN (FFN1 emits fp16 intermediate)
        gemm_tc<<<dim3(DFFd / 128, NTOK / 128), 256>>>(
            x16, Dd, w16 + OW1 + (size_t)i * DFFd * Dd, Dd,
            b1 + (size_t)i * DFFd, ffn16, DFFd, Dd, 1, 1);
        gemm_tc<<<dim3(Dd / 128, NTOK / 128), 256>>>(
            ffn16, DFFd, w16 + OW2 + (size_t)i * Dd * DFFd, DFFd,
            b2 + (size_t)i * Dd, tmp, Dd, DFFd, 0, 0);

        // residual + LN2 (final layer writes straight to d_out)
        add_ln<<<NTOK, 256>>>(x, tmp, ln2s + (size_t)i * Dd, ln2b + (size_t)i * Dd,
                              (i == Ll - 1) ? out : x, (__half*)nullptr, 0, 0);
    }
    (void)in_sizes; (void)n_in; (void)out_size;
}